// round 14
// baseline (speedup 1.0000x reference)
#include <cuda_runtime.h>

// LIF SNN scan: T=1024 timesteps, B*N = 65536 independent columns.
// out layout: [ spikes (T*BN) | v_final (BN) | i_final (BN) ]
// R14: R9 body (float2, rolling PF=32 ring — converged SM-side optimum) plus
// L2 prefetch PD=96 steps ahead: prefetch.global.L2 has no dest register and
// never blocks (unlike LDG past the ~55/warp accept cap, which stalled R5/R12),
// so it deepens the DRAM read queue and converts demand misses to L2 hits
// without starving the store stream. Lanes 0/16 cover the warp's 2 lines.

#define T_STEPS 1024
#define BN      65536
#define NCOL2   (BN / 2)    // float2 columns
#define PF      32
#define PD      96          // prefetch distance beyond the ring (timesteps)

__device__ __forceinline__ void l2_prefetch(const float2* p) {
    asm volatile("prefetch.global.L2 [%0];" :: "l"(p));
}

__global__ __launch_bounds__(64, 4)
void snn_lif_kernel(const float2* __restrict__ x, float2* __restrict__ out) {
    const int idx = blockIdx.x * blockDim.x + threadIdx.x;  // float2-column id
    const float2* xp = x + idx;
    float2*       zp = out + idx;
    const bool pf_lane = ((threadIdx.x & 15) == 0);  // 2 lanes/warp = 2x128B lines

    float v0 = 0.0f, v1 = 0.0f;     // membrane potentials
    float c0 = 0.0f, c1 = 0.0f;     // synaptic currents

    // prologue: fill the prefetch ring (32 independent LDG.64 in flight)
    float2 xbuf[PF];
    #pragma unroll
    for (int j = 0; j < PF; ++j)
        xbuf[j] = __ldg(xp + (long)j * NCOL2);

    // warm the L2 ahead-window for the first chunks
    if (pf_lane) {
        for (int t = PF; t < PF + PD; t += 4)   // coarse warmup, 4-step stride
            l2_prefetch(xp + (long)t * NCOL2);
    }

    // dt*tau_mem_inv = 0.1, (1 - dt*tau_syn_inv) = 0.8, v_th = 1, v_reset = 0
    for (int t0 = 0; t0 < T_STEPS - PF; t0 += PF) {
        #pragma unroll
        for (int j = 0; j < PF; ++j) {
            const float2 xt = xbuf[j];
            // demand load for t0+PF+j (ring stays full; should hit L2 now)
            xbuf[j] = __ldg(xp + (long)(t0 + PF + j) * NCOL2);

            // stream the L2 ahead-window forward (droppable, non-blocking)
            if (pf_lane) {
                int tpre = t0 + PF + j + PD;
                if (tpre >= T_STEPS) tpre = T_STEPS - 1;
                l2_prefetch(xp + (long)tpre * NCOL2);
            }

            float2 z;

            const float vd0 = fmaf(0.1f, c0 - v0, v0);
            const bool  f0  = (vd0 > 1.0f);
            z.x = f0 ? 1.0f : 0.0f;
            v0  = f0 ? 0.0f : vd0;
            c0  = fmaf(c0, 0.8f, xt.x);

            const float vd1 = fmaf(0.1f, c1 - v1, v1);
            const bool  f1  = (vd1 > 1.0f);
            z.y = f1 ? 1.0f : 0.0f;
            v1  = f1 ? 0.0f : vd1;
            c1  = fmaf(c1, 0.8f, xt.y);

            zp[(long)(t0 + j) * NCOL2] = z;
        }
    }

    // epilogue: last PF steps, no prefetch
    #pragma unroll
    for (int j = 0; j < PF; ++j) {
        const float2 xt = xbuf[j];

        float2 z;

        const float vd0 = fmaf(0.1f, c0 - v0, v0);
        const bool  f0  = (vd0 > 1.0f);
        z.x = f0 ? 1.0f : 0.0f;
        v0  = f0 ? 0.0f : vd0;
        c0  = fmaf(c0, 0.8f, xt.x);

        const float vd1 = fmaf(0.1f, c1 - v1, v1);
        const bool  f1  = (vd1 > 1.0f);
        z.y = f1 ? 1.0f : 0.0f;
        v1  = f1 ? 0.0f : vd1;
        c1  = fmaf(c1, 0.8f, xt.y);

        zp[(long)(T_STEPS - PF + j) * NCOL2] = z;
    }

    // final state after the full scan: v then i, each BN floats (NCOL2 float2)
    float2 vf; vf.x = v0; vf.y = v1;
    float2 cf; cf.x = c0; cf.y = c1;
    out[(long)T_STEPS * NCOL2 + idx]          = vf;
    out[(long)T_STEPS * NCOL2 + NCOL2 + idx]  = cf;
}

extern "C" void kernel_launch(void* const* d_in, const int* in_sizes, int n_in,
                              void* d_out, int out_size) {
    const float2* x   = (const float2*)d_in[0];
    float2*       out = (float2*)d_out;
    (void)in_sizes; (void)n_in; (void)out_size;

    snn_lif_kernel<<<NCOL2 / 64, 64>>>(x, out);
}

// round 15
// speedup vs baseline: 1.1976x; 1.1976x over previous
#include <cuda_runtime.h>

// LIF SNN scan: T=1024 timesteps, B*N = 65536 independent columns.
// out layout: [ spikes (T*BN) | v_final (BN) | i_final (BN) ]
// FINAL (== R9, best measured: bench 86.5us, kernel 76.2us, DRAM 80.3%).
// float2 columns, rolling software-prefetch ring PF=32, plain __ldg/STG.
// Converged after a closed experiment matrix: ring depth {16,32,64} peaks at
// 32 (past ~55/warp LDG accept cap the warp hard-stalls and starves stores);
// width {f1,f2,f4} peaks at f2; phase batching, cache hints (__ldcs/__stcs),
// wave rebalancing, and L2 prefetch (breaks ptxas's front-batched schedule —
// regs 143->115) all regress. 6.3 TB/s ~= 80% of HBM spec on a 50/50 R/W mix
// is the controller-side ceiling; 512 MB mandatory traffic -> 64us spec floor,
// this kernel runs at 84% of it.

#define T_STEPS 1024
#define BN      65536
#define NCOL2   (BN / 2)    // float2 columns
#define PF      32

__global__ __launch_bounds__(64, 4)
void snn_lif_kernel(const float2* __restrict__ x, float2* __restrict__ out) {
    const int idx = blockIdx.x * blockDim.x + threadIdx.x;  // float2-column id
    const float2* xp = x + idx;
    float2*       zp = out + idx;

    float v0 = 0.0f, v1 = 0.0f;     // membrane potentials
    float c0 = 0.0f, c1 = 0.0f;     // synaptic currents

    // prologue: fill the prefetch ring (32 independent LDG.64 in flight)
    float2 xbuf[PF];
    #pragma unroll
    for (int j = 0; j < PF; ++j)
        xbuf[j] = __ldg(xp + (long)j * NCOL2);

    // dt*tau_mem_inv = 0.1, (1 - dt*tau_syn_inv) = 0.8, v_th = 1, v_reset = 0
    for (int t0 = 0; t0 < T_STEPS - PF; t0 += PF) {
        #pragma unroll
        for (int j = 0; j < PF; ++j) {
            const float2 xt = xbuf[j];
            // immediately re-issue this slot for t0+PF+j (ring stays full)
            xbuf[j] = __ldg(xp + (long)(t0 + PF + j) * NCOL2);

            float2 z;

            const float vd0 = fmaf(0.1f, c0 - v0, v0);
            const bool  f0  = (vd0 > 1.0f);
            z.x = f0 ? 1.0f : 0.0f;
            v0  = f0 ? 0.0f : vd0;
            c0  = fmaf(c0, 0.8f, xt.x);

            const float vd1 = fmaf(0.1f, c1 - v1, v1);
            const bool  f1  = (vd1 > 1.0f);
            z.y = f1 ? 1.0f : 0.0f;
            v1  = f1 ? 0.0f : vd1;
            c1  = fmaf(c1, 0.8f, xt.y);

            zp[(long)(t0 + j) * NCOL2] = z;
        }
    }

    // epilogue: last PF steps, no prefetch
    #pragma unroll
    for (int j = 0; j < PF; ++j) {
        const float2 xt = xbuf[j];

        float2 z;

        const float vd0 = fmaf(0.1f, c0 - v0, v0);
        const bool  f0  = (vd0 > 1.0f);
        z.x = f0 ? 1.0f : 0.0f;
        v0  = f0 ? 0.0f : vd0;
        c0  = fmaf(c0, 0.8f, xt.x);

        const float vd1 = fmaf(0.1f, c1 - v1, v1);
        const bool  f1  = (vd1 > 1.0f);
        z.y = f1 ? 1.0f : 0.0f;
        v1  = f1 ? 0.0f : vd1;
        c1  = fmaf(c1, 0.8f, xt.y);

        zp[(long)(T_STEPS - PF + j) * NCOL2] = z;
    }

    // final state after the full scan: v then i, each BN floats (NCOL2 float2)
    float2 vf; vf.x = v0; vf.y = v1;
    float2 cf; cf.x = c0; cf.y = c1;
    out[(long)T_STEPS * NCOL2 + idx]          = vf;
    out[(long)T_STEPS * NCOL2 + NCOL2 + idx]  = cf;
}

extern "C" void kernel_launch(void* const* d_in, const int* in_sizes, int n_in,
                              void* d_out, int out_size) {
    const float2* x   = (const float2*)d_in[0];
    float2*       out = (float2*)d_out;
    (void)in_sizes; (void)n_in; (void)out_size;

    snn_lif_kernel<<<NCOL2 / 64, 64>>>(x, out);
}

// round 16
// speedup vs baseline: 1.2070x; 1.0078x over previous
#include <cuda_runtime.h>

// LIF SNN scan: T=1024 timesteps, B*N = 65536 independent columns.
// out layout: [ spikes (T*BN) | v_final (BN) | i_final (BN) ]
// FINAL (== R9; best measured, reproduced 3x: bench 86.5-86.8us, kernel
// 76.2-77.7us, DRAM 78-80%). float2 columns, rolling software-prefetch ring
// PF=32, plain __ldg/STG, block 64.
//
// Converged after a closed experiment matrix (7 falsified mechanisms):
//   ring depth {16,32,64} -> peak 32 (past the ~55/warp LDG accept cap the
//     warp hard-stalls at the LSU and starves the store stream);
//   width {f1,f2,f4} -> peak f2 (LSU-ops-per-byte vs warps/SM tradeoff);
//   phase batching -> drains in-flight loads (-7%);
//   __ldcs -> ptxas stops batching loads (MLP collapses to 1);
//   __stcs -> -1%;  wave rebalance (4v3 vs 7v6 CTA/SM) -> immaterial;
//   L2 prefetch in-body -> breaks the front-batched schedule (regs 143->115).
// 6.3 TB/s ~= 80% of HBM spec on a 50/50 R/W mix is the DRAM-controller
// ceiling; 512 MB mandatory traffic -> 64us spec floor; this runs at 84% of it.

#define T_STEPS 1024
#define BN      65536
#define NCOL2   (BN / 2)    // float2 columns
#define PF      32

__global__ __launch_bounds__(64, 4)
void snn_lif_kernel(const float2* __restrict__ x, float2* __restrict__ out) {
    const int idx = blockIdx.x * blockDim.x + threadIdx.x;  // float2-column id
    const float2* xp = x + idx;
    float2*       zp = out + idx;

    float v0 = 0.0f, v1 = 0.0f;     // membrane potentials
    float c0 = 0.0f, c1 = 0.0f;     // synaptic currents

    // prologue: fill the prefetch ring (32 independent LDG.64 in flight)
    float2 xbuf[PF];
    #pragma unroll
    for (int j = 0; j < PF; ++j)
        xbuf[j] = __ldg(xp + (long)j * NCOL2);

    // dt*tau_mem_inv = 0.1, (1 - dt*tau_syn_inv) = 0.8, v_th = 1, v_reset = 0
    for (int t0 = 0; t0 < T_STEPS - PF; t0 += PF) {
        #pragma unroll
        for (int j = 0; j < PF; ++j) {
            const float2 xt = xbuf[j];
            // immediately re-issue this slot for t0+PF+j (ring stays full)
            xbuf[j] = __ldg(xp + (long)(t0 + PF + j) * NCOL2);

            float2 z;

            const float vd0 = fmaf(0.1f, c0 - v0, v0);
            const bool  f0  = (vd0 > 1.0f);
            z.x = f0 ? 1.0f : 0.0f;
            v0  = f0 ? 0.0f : vd0;
            c0  = fmaf(c0, 0.8f, xt.x);

            const float vd1 = fmaf(0.1f, c1 - v1, v1);
            const bool  f1  = (vd1 > 1.0f);
            z.y = f1 ? 1.0f : 0.0f;
            v1  = f1 ? 0.0f : vd1;
            c1  = fmaf(c1, 0.8f, xt.y);

            zp[(long)(t0 + j) * NCOL2] = z;
        }
    }

    // epilogue: last PF steps, no prefetch
    #pragma unroll
    for (int j = 0; j < PF; ++j) {
        const float2 xt = xbuf[j];

        float2 z;

        const float vd0 = fmaf(0.1f, c0 - v0, v0);
        const bool  f0  = (vd0 > 1.0f);
        z.x = f0 ? 1.0f : 0.0f;
        v0  = f0 ? 0.0f : vd0;
        c0  = fmaf(c0, 0.8f, xt.x);

        const float vd1 = fmaf(0.1f, c1 - v1, v1);
        const bool  f1  = (vd1 > 1.0f);
        z.y = f1 ? 1.0f : 0.0f;
        v1  = f1 ? 0.0f : vd1;
        c1  = fmaf(c1, 0.8f, xt.y);

        zp[(long)(T_STEPS - PF + j) * NCOL2] = z;
    }

    // final state after the full scan: v then i, each BN floats (NCOL2 float2)
    float2 vf; vf.x = v0; vf.y = v1;
    float2 cf; cf.x = c0; cf.y = c1;
    out[(long)T_STEPS * NCOL2 + idx]          = vf;
    out[(long)T_STEPS * NCOL2 + NCOL2 + idx]  = cf;
}

extern "C" void kernel_launch(void* const* d_in, const int* in_sizes, int n_in,
                              void* d_out, int out_size) {
    const float2* x   = (const float2*)d_in[0];
    float2*       out = (float2*)d_out;
    (void)in_sizes; (void)n_in; (void)out_size;

    snn_lif_kernel<<<NCOL2 / 64, 64>>>(x, out);
}